// round 11
// baseline (speedup 1.0000x reference)
#include <cuda_runtime.h>
#include <cstdint>

// SplineActivation: y[b,w] = clamped cubic B-spline (16 uniform knots on [-3,3],
// degree 3) of x[b,w], per-channel coefficients coefs[w, 0..17].
//
// Round-11: R5 retried with the bank conflict actually fixed. float4 I/O
// (LDG.128/STG.128, 4 channels/thread) cuts I/O wavefronts 4x; the table is
// stored PERMUTED: channel 4*col+e lives at smem slot e*32+col, so gather
// instruction e addresses k*2048 + (e*32+col)*16 -> 16B lane stride, exactly
// R6's proven conflict-free LDS.128 pattern, for every e. Build kernel and
// launch setup identical to the proven R6 configuration.

#define W_TOTAL  1024
#define B_TOTAL  8192
#define NB_IV    15
#define CH       128
#define BD       256
#define N_CTRL   18
#define GY       92           // 8 x 92 = 736 CTAs ~= 5 per SM

__device__ float4 g_poly[NB_IV * W_TOTAL];   // [interval][channel] monomial cubic

// ---------------------------------------------------------------------------
// Fused build (unchanged, proven): 15x4 conversion cubics in smem, one g_poly
// entry per thread. Grid 60 x 256.
// ---------------------------------------------------------------------------
__global__ __launch_bounds__(BD)
void build_poly_kernel(const float* __restrict__ coefs) {
    __shared__ float4 M[NB_IV * 4];
    const int t = threadIdx.x;

    if (t < NB_IV * 4) {
        const int k = t >> 2;
        const int j = t & 3;

        float tk[22];
#pragma unroll
        for (int m = 0; m < 16; m++)
            tk[3 + m] = (float)(-3.0 + (double)m * (6.0 / 15.0));
        tk[0] = tk[1] = tk[2] = tk[3];
        tk[19] = tk[20] = tk[21] = tk[18];

        const int   kg    = k + 3;
        const float x0    = tk[kg];
        const float delta = (tk[kg + 1] - tk[kg]) * (1.0f / 3.0f);
        const float Kev   = fmaf((float)k, 0.4f, -3.0f);

        float f[4];
#pragma unroll
        for (int m = 0; m < 4; m++) {
            float x = x0 + delta * (float)m;
            float left[3], right[3];
#pragma unroll
            for (int i2 = 1; i2 <= 3; i2++) {
                left [i2 - 1] = x - tk[kg + 1 - i2];
                right[i2 - 1] = tk[kg + i2] - x;
            }
            float N[4];
            N[0] = 1.0f;
#pragma unroll
            for (int jj = 1; jj <= 3; jj++) {
                float saved = 0.0f;
#pragma unroll
                for (int r = 0; r < jj; r++) {
                    float temp = N[r] / (right[r] + left[jj - 1 - r]);
                    N[r] = saved + right[r] * temp;
                    saved = left[jj - 1 - r] * temp;
                }
                N[jj] = saved;
            }
            f[m] = N[j];
        }

        const float id = 1.0f / delta;
        const float d1 = (f[1] - f[0]) * id;
        const float d2 = (f[2] - 2.0f * f[1] + f[0]) * (0.5f * id * id);
        const float d3 = (f[3] - 3.0f * f[2] + 3.0f * f[1] - f[0])
                         * ((1.0f / 6.0f) * id * id * id);
        const float a0 = f[0];
        const float a1 = d1 - delta * d2 + 2.0f * delta * delta * d3;
        const float a2 = d2 - 3.0f * delta * d3;
        const float a3 = d3;

        const float s0 = x0 - Kev;
        const float b3 = a3;
        const float b2 = a2 - 3.0f * a3 * s0;
        const float b1 = a1 - 2.0f * a2 * s0 + 3.0f * a3 * s0 * s0;
        const float b0 = a0 - a1 * s0 + a2 * s0 * s0 - a3 * s0 * s0 * s0;

        M[t] = make_float4(b0, b1, b2, b3);
    }
    __syncthreads();

    const int idx = blockIdx.x * BD + t;
    const int c   = idx & (W_TOTAL - 1);
    const int k   = idx >> 10;

    float4 acc = make_float4(0.f, 0.f, 0.f, 0.f);
#pragma unroll
    for (int j = 0; j < 4; j++) {
        float  cf = __ldg(&coefs[c * N_CTRL + k + j]);
        float4 m  = M[k * 4 + j];
        acc.x = fmaf(cf, m.x, acc.x);
        acc.y = fmaf(cf, m.y, acc.y);
        acc.z = fmaf(cf, m.z, acc.z);
        acc.w = fmaf(cf, m.w, acc.w);
    }
    g_poly[k * W_TOTAL + c] = acc;
}

// ---------------------------------------------------------------------------
// Hot kernel. 256 threads: col = t&31 owns channels c0 + 4*col .. +3 (one
// float4 of X/Y per row); rg = t>>5 picks a row sub-group (8 groups, 4-row
// unroll -> 32 rows per block-iteration). Table permuted: channel 4*col+e at
// smem slot [k][e*32+col] -> every gather instruction has 16B lane stride,
// k-stride 2048B -> conflict-free for any per-lane k (R6's proven pattern).
// ---------------------------------------------------------------------------
__device__ __forceinline__ float eval_one(float x, const float4* sp_k_base) {
    // sp_k_base points at sp[0][slot] for this element's slot; stride between
    // intervals is CH float4s.
    float fi = floorf(fmaf(x, 2.5f, 7.5f));
    fi       = fminf(fmaxf(fi, 0.0f), 14.0f);
    int   k  = (int)fi;
    float s  = x - fmaf(fi, 0.4f, -3.0f);
    float4 p = sp_k_base[k * CH];
    return fmaf(fmaf(fmaf(p.w, s, p.z), s, p.y), s, p.x);
}

__global__ __launch_bounds__(BD, 5)
void spline_eval_kernel(const float* __restrict__ X, float* __restrict__ Y) {
    __shared__ float4 sp[NB_IV][CH];         // 30,720 B
    const int t  = threadIdx.x;
    const int c0 = blockIdx.x * CH;

    // Stage with permutation: slot s = e*32+col holds channel 4*col+e.
    for (int i = t; i < NB_IV * CH; i += BD) {
        const int k  = i >> 7;
        const int s  = i & (CH - 1);
        const int e  = s >> 5;
        const int cl = s & 31;
        sp[k][s] = g_poly[k * W_TOTAL + c0 + 4 * cl + e];
    }
    __syncthreads();

    const int col = t & 31;
    const int rg  = t >> 5;                  // 0..7
    const float4* sp0 = &sp[0][col];         // slot for e=0; e adds 32
    const float4* sp1 = &sp[0][32 + col];
    const float4* sp2 = &sp[0][64 + col];
    const float4* sp3 = &sp[0][96 + col];

    const float4* Xv = (const float4*)X;
    float4*       Yv = (float4*)Y;
    const int vrow  = W_TOTAL / 4;           // 256 float4 per row
    const int vcol  = (c0 >> 2) + col;
    const int rstep = gridDim.y * 32;

    for (int base = blockIdx.y * 32; base < B_TOTAL; base += rstep) {
        const int r0 = base + rg;            // rows r0, r0+8, r0+16, r0+24

        float4 xv[4];
#pragma unroll
        for (int q = 0; q < 4; q++)
            xv[q] = Xv[(size_t)(r0 + 8 * q) * vrow + vcol];

#pragma unroll
        for (int q = 0; q < 4; q++) {
            float4 r;
            r.x = eval_one(xv[q].x, sp0);
            r.y = eval_one(xv[q].y, sp1);
            r.z = eval_one(xv[q].z, sp2);
            r.w = eval_one(xv[q].w, sp3);
            xv[q] = r;
        }

#pragma unroll
        for (int q = 0; q < 4; q++)
            Yv[(size_t)(r0 + 8 * q) * vrow + vcol] = xv[q];
    }
}

// ---------------------------------------------------------------------------
extern "C" void kernel_launch(void* const* d_in, const int* in_sizes, int n_in,
                              void* d_out, int out_size) {
    const float* X     = (const float*)d_in[0];
    const float* coefs = (const float*)d_in[1];
    if (n_in >= 2 && in_sizes[0] < in_sizes[1]) {   // identify by size
        X     = (const float*)d_in[1];
        coefs = (const float*)d_in[0];
    }
    float* Y = (float*)d_out;

    build_poly_kernel<<<NB_IV * W_TOTAL / BD, BD>>>(coefs);   // 60 x 256

    dim3 grid(W_TOTAL / CH, GY);             // 8 x 92 = 736 CTAs
    spline_eval_kernel<<<grid, BD>>>(X, Y);
}